// round 3
// baseline (speedup 1.0000x reference)
#include <cuda_runtime.h>
#include <cuda_fp16.h>
#include <cstdint>

// ---------------------------------------------------------------------------
// GeoEncoder: tri-plane + line sampling, rank 48 (padded to 64), OUT=32.
// Strategy:
//   1) transpose planes [48,512,512] fp32 -> [512,512,64] half (zero-padded)
//      so one (y,x) tap == one 128B line.  72->96MB, mostly L2 resident.
//   2) transpose lines [48,512] -> [512,64] half (one row == one 128B line).
//   3) sample kernel: 8 lanes per point, each lane owns an 8-rank octet.
//      All 8 lanes of a point read the same 128B line per tap -> L1tex
//      wavefront merging. Interp in HFMA2, accumulate in fp32.
//      Matvec via smem-staged vm + packed fma.rn.f32x2 (FFMA2).
// ---------------------------------------------------------------------------

#define RES 512
#define RANKP 64              // padded rank (halves) per (y,x)
#define RP2 32                // half2 per (y,x)

// 3 * 512 * 512 * 32 half2 = 96 MB
__device__ __align__(128) __half2 g_tplanes[(size_t)3 * RES * RES * RP2];
// 3 * 512 * 32 half2 = 192 KB
__device__ __align__(128) __half2 g_tlines[3 * RES * RP2];

// ---- packed fp32x2 helpers (Blackwell FFMA2) ------------------------------
__device__ __forceinline__ float2 ffma2(float2 a, float2 b, float2 c) {
    unsigned long long A = *reinterpret_cast<unsigned long long*>(&a);
    unsigned long long B = *reinterpret_cast<unsigned long long*>(&b);
    unsigned long long C = *reinterpret_cast<unsigned long long*>(&c);
    unsigned long long D;
    asm("fma.rn.f32x2 %0, %1, %2, %3;" : "=l"(D) : "l"(A), "l"(B), "l"(C));
    return *reinterpret_cast<float2*>(&D);
}
__device__ __forceinline__ float2 fadd2(float2 a, float2 b) {
    unsigned long long A = *reinterpret_cast<unsigned long long*>(&a);
    unsigned long long B = *reinterpret_cast<unsigned long long*>(&b);
    unsigned long long D;
    asm("add.rn.f32x2 %0, %1, %2;" : "=l"(D) : "l"(A), "l"(B));
    return *reinterpret_cast<float2*>(&D);
}

// ---------------------------------------------------------------------------
// Transpose planes: [48,512,512] fp32 -> [512,512,64] half (pad ranks 48..63=0)
// grid (16, 512, 3), block 256.  Tile: 48 ranks x 32 x for one y.
// ---------------------------------------------------------------------------
__global__ __launch_bounds__(256) void transpose_planes(
    const float* __restrict__ p0, const float* __restrict__ p1,
    const float* __restrict__ p2)
{
    __shared__ float sh[32][49];   // [x][r], stride 49 -> conflict-free
    const int xbase = blockIdx.x * 32;
    const int y     = blockIdx.y;
    const int pl    = blockIdx.z;
    const float* src = (pl == 0) ? p0 : ((pl == 1) ? p1 : p2);
    const int tid = threadIdx.x;

    #pragma unroll
    for (int i = 0; i < 6; i++) {
        int e = tid + i * 256;          // 0..1535
        int r = e >> 5;                 // 0..47
        int x = e & 31;
        sh[x][r] = src[(size_t)r * (RES * RES) + y * RES + xbase + x];
    }
    __syncthreads();

    const size_t obase = ((size_t)(pl * RES + y) * RES + xbase) * RP2; // half2 units
    #pragma unroll
    for (int i = 0; i < 4; i++) {
        int t  = tid + i * 256;         // 0..1023
        int x  = t >> 5;                // 0..31
        int rp = t & 31;                // 0..31 (rank pair)
        float a = 0.f, b = 0.f;
        if (rp < 24) { a = sh[x][2 * rp]; b = sh[x][2 * rp + 1]; }
        g_tplanes[obase + (size_t)x * RP2 + rp] = __floats2half2_rn(a, b);
    }
}

// ---------------------------------------------------------------------------
// Transpose lines: [48,512] fp32 -> [512,64] half.  One thread per half2 out.
// grid 192, block 256  (3 * 512 * 32 = 49152 half2)
// ---------------------------------------------------------------------------
__global__ __launch_bounds__(256) void transpose_lines(
    const float* __restrict__ lz, const float* __restrict__ ly,
    const float* __restrict__ lx)
{
    int idx = blockIdx.x * 256 + threadIdx.x;       // 0..49151
    int pl  = idx >> 14;                            // /16384
    int rem = idx & 16383;
    int y   = rem >> 5;
    int rp  = rem & 31;
    const float* src = (pl == 0) ? lz : ((pl == 1) ? ly : lx);
    float a = 0.f, b = 0.f;
    if (rp < 24) { a = src[(2 * rp) * RES + y]; b = src[(2 * rp + 1) * RES + y]; }
    g_tlines[idx] = __floats2half2_rn(a, b);
}

// ---------------------------------------------------------------------------
// Sampling kernel: 8 lanes per point (sub = lane&7 owns ranks [8*sub, 8*sub+8))
// block 256 -> 32 points per block.
// ---------------------------------------------------------------------------
struct Axis { int i0, i1; float w; };

__device__ __forceinline__ Axis make_axis(float c) {
    float t = c * 2.f - 1.f;                       // replicate reference math
    float p = (t + 1.f) * 0.5f * (float)(RES - 1);
    p = fminf(fmaxf(p, 0.f), (float)(RES - 1));
    float f = floorf(p);
    Axis a;
    a.i0 = (int)f;
    a.i1 = min(a.i0 + 1, RES - 1);
    a.w  = p - f;
    return a;
}

__device__ __forceinline__ void plane_accum(
    int pl, int row0, int row1, float wr,
    int col0, int col1, float wc,
    int lnp, int li0, int li1, float wl,
    int sub, float2* vm)
{
    const int pb = pl * (RES * RES * RP2);
    const int o00 = pb + (row0 * RES + col0) * RP2 + sub * 4;
    const int o01 = pb + (row0 * RES + col1) * RP2 + sub * 4;
    const int o10 = pb + (row1 * RES + col0) * RP2 + sub * 4;
    const int o11 = pb + (row1 * RES + col1) * RP2 + sub * 4;

    // gather taps: one 16B load per tap per lane; 8 lanes share the 128B line.
    uint4 t00 = __ldcg((const uint4*)(g_tplanes + o00));
    uint4 t01 = __ldcg((const uint4*)(g_tplanes + o01));
    uint4 t10 = __ldcg((const uint4*)(g_tplanes + o10));
    uint4 t11 = __ldcg((const uint4*)(g_tplanes + o11));

    const int lb = lnp * (RES * RP2) + sub * 4;
    uint4 L0 = *(const uint4*)(g_tlines + lb + li0 * RP2);
    uint4 L1 = *(const uint4*)(g_tlines + lb + li1 * RP2);

    const __half2 hw00 = __float2half2_rn((1.f - wr) * (1.f - wc));
    const __half2 hw01 = __float2half2_rn((1.f - wr) * wc);
    const __half2 hw10 = __float2half2_rn(wr * (1.f - wc));
    const __half2 hw11 = __float2half2_rn(wr * wc);
    const __half2 hwl  = __float2half2_rn(wl);

    const __half2* a00 = (const __half2*)&t00;
    const __half2* a01 = (const __half2*)&t01;
    const __half2* a10 = (const __half2*)&t10;
    const __half2* a11 = (const __half2*)&t11;
    const __half2* l0p = (const __half2*)&L0;
    const __half2* l1p = (const __half2*)&L1;

    #pragma unroll
    for (int k = 0; k < 4; k++) {
        __half2 v = __hmul2(hw00, a00[k]);
        v = __hfma2(hw01, a01[k], v);
        v = __hfma2(hw10, a10[k], v);
        v = __hfma2(hw11, a11[k], v);
        __half2 l = __hfma2(hwl, __hsub2(l1p[k], l0p[k]), l0p[k]);
        float2 p = __half22float2(__hmul2(v, l));
        vm[k] = fadd2(vm[k], p);
    }
}

__global__ __launch_bounds__(256) void geo_sample(
    const float* __restrict__ coords,
    const float* __restrict__ W,      // [32,48]
    const float* __restrict__ B,      // [32]
    float* __restrict__ out,          // [N,32]
    int npts)
{
    __shared__ float2 Wpair[24][32];  // Wpair[rp][o] = (W[o][2rp], W[o][2rp+1])
    __shared__ float  vmsh[32][68];   // padded: conflict-free f32x2 reads
    __shared__ float  bsh[32];

    const int tid = threadIdx.x;
    for (int i = tid; i < 768; i += 256) {
        int o = i & 31, rp = i >> 5;
        Wpair[rp][o] = make_float2(W[o * 48 + 2 * rp], W[o * 48 + 2 * rp + 1]);
    }
    if (tid < 32) bsh[tid] = B[tid];
    __syncthreads();

    const int sub = tid & 7;          // rank octet
    const int lpt = tid >> 3;         // local point 0..31
    const int pt  = blockIdx.x * 32 + lpt;
    const bool valid = (pt < npts);

    float cx = 0.f, cy = 0.f, cz = 0.f;
    if (valid) {
        cx = coords[pt * 3 + 0];
        cy = coords[pt * 3 + 1];
        cz = coords[pt * 3 + 2];
    }
    Axis ax = make_axis(cx);
    Axis ay = make_axis(cy);
    Axis az = make_axis(cz);

    float2 vm[4];
    #pragma unroll
    for (int k = 0; k < 4; k++) vm[k] = make_float2(0.f, 0.f);

    // plane_xy(cx,cy)*line_z + plane_xz(cx,cz)*line_y + plane_yz(cy,cz)*line_x
    plane_accum(0, ay.i0, ay.i1, ay.w, ax.i0, ax.i1, ax.w, 0, az.i0, az.i1, az.w, sub, vm);
    plane_accum(1, az.i0, az.i1, az.w, ax.i0, ax.i1, ax.w, 1, ay.i0, ay.i1, ay.w, sub, vm);
    plane_accum(2, az.i0, az.i1, az.w, ay.i0, ay.i1, ay.w, 2, ax.i0, ax.i1, ax.w, sub, vm);

    // stage vm octet to smem
    *(float4*)&vmsh[lpt][sub * 8]     = make_float4(vm[0].x, vm[0].y, vm[1].x, vm[1].y);
    *(float4*)&vmsh[lpt][sub * 8 + 4] = make_float4(vm[2].x, vm[2].y, vm[3].x, vm[3].y);
    __syncwarp();

    // matvec: each lane produces outputs o = 4*sub .. 4*sub+3 via FFMA2
    float2 a0 = make_float2(0.f, 0.f), a1 = a0, a2 = a0, a3 = a0;
    #pragma unroll
    for (int rp = 0; rp < 24; rp++) {
        float2 v  = *(const float2*)&vmsh[lpt][2 * rp];
        float4 wA = *(const float4*)&Wpair[rp][sub * 4];
        float4 wB = *(const float4*)&Wpair[rp][sub * 4 + 2];
        a0 = ffma2(v, make_float2(wA.x, wA.y), a0);
        a1 = ffma2(v, make_float2(wA.z, wA.w), a1);
        a2 = ffma2(v, make_float2(wB.x, wB.y), a2);
        a3 = ffma2(v, make_float2(wB.z, wB.w), a3);
    }

    if (valid) {
        const int o0 = sub * 4;
        float4 res;
        res.x = a0.x + a0.y + bsh[o0 + 0];
        res.y = a1.x + a1.y + bsh[o0 + 1];
        res.z = a2.x + a2.y + bsh[o0 + 2];
        res.w = a3.x + a3.y + bsh[o0 + 3];
        *(float4*)(out + (size_t)pt * 32 + o0) = res;
    }
}

// ---------------------------------------------------------------------------
extern "C" void kernel_launch(void* const* d_in, const int* in_sizes, int n_in,
                              void* d_out, int out_size)
{
    const float* coords  = (const float*)d_in[0];
    const float* pxy     = (const float*)d_in[1];
    const float* pxz     = (const float*)d_in[2];
    const float* pyz     = (const float*)d_in[3];
    const float* lz      = (const float*)d_in[4];
    const float* ly      = (const float*)d_in[5];
    const float* lx      = (const float*)d_in[6];
    const float* projw   = (const float*)d_in[7];
    const float* projb   = (const float*)d_in[8];
    float* out = (float*)d_out;

    const int npts = in_sizes[0] / 3;

    transpose_planes<<<dim3(16, 512, 3), 256>>>(pxy, pxz, pyz);
    transpose_lines<<<192, 256>>>(lz, ly, lx);

    const int nblocks = (npts + 31) / 32;
    geo_sample<<<nblocks, 256>>>(coords, projw, projb, out, npts);
}

// round 4
// speedup vs baseline: 1.0381x; 1.0381x over previous
#include <cuda_runtime.h>
#include <cuda_fp16.h>
#include <cstdint>

// ---------------------------------------------------------------------------
// GeoEncoder: tri-plane + line sampling, rank 48 (padded to 64), OUT=32.
//   1) transpose planes [48,512,512] fp32 -> [512,512,64] half (zero-padded)
//      so one (y,x) tap == one 128B line (L2-resident, 96MB).
//   2) transpose lines [48,512] fp32 -> [512,64] half (L1-resident, 192KB).
//   3) geo_sample: 8 lanes per point, lane owns an 8-rank octet.
//      R3 change: ALL 18 loads (12 plane taps + 6 line rows) issued
//      back-to-back before any interpolation -> MLP 18/lane, single
//      exposed L2 latency per point instead of ~3.
// ---------------------------------------------------------------------------

#define RES 512
#define RP2 32                // half2 per (y,x) texel (64 halves = 128B)

__device__ __align__(128) __half2 g_tplanes[(size_t)3 * RES * RES * RP2];
__device__ __align__(128) __half2 g_tlines[3 * RES * RP2];

// ---- packed fp32x2 helpers (Blackwell FFMA2) ------------------------------
__device__ __forceinline__ float2 ffma2(float2 a, float2 b, float2 c) {
    unsigned long long A = *reinterpret_cast<unsigned long long*>(&a);
    unsigned long long B = *reinterpret_cast<unsigned long long*>(&b);
    unsigned long long C = *reinterpret_cast<unsigned long long*>(&c);
    unsigned long long D;
    asm("fma.rn.f32x2 %0, %1, %2, %3;" : "=l"(D) : "l"(A), "l"(B), "l"(C));
    return *reinterpret_cast<float2*>(&D);
}
__device__ __forceinline__ float2 fadd2(float2 a, float2 b) {
    unsigned long long A = *reinterpret_cast<unsigned long long*>(&a);
    unsigned long long B = *reinterpret_cast<unsigned long long*>(&b);
    unsigned long long D;
    asm("add.rn.f32x2 %0, %1, %2;" : "=l"(D) : "l"(A), "l"(B));
    return *reinterpret_cast<float2*>(&D);
}

// ---------------------------------------------------------------------------
// Transpose planes (R3: float4 loads, uint4 stores).
// grid (16, 512, 3), block 256. Tile: one y row, 32 x, 48 ranks.
// ---------------------------------------------------------------------------
__global__ __launch_bounds__(256) void transpose_planes(
    const float* __restrict__ p0, const float* __restrict__ p1,
    const float* __restrict__ p2)
{
    __shared__ float sh[32][49];   // [x][r]
    const int xbase = blockIdx.x * 32;
    const int y     = blockIdx.y;
    const int pl    = blockIdx.z;
    const float* __restrict__ src = (pl == 0) ? p0 : ((pl == 1) ? p1 : p2);
    const int tid = threadIdx.x;

    // Load 48r x 32x = 384 float4 (each warp: 4 ranks x 8 float4 = coalesced 128B)
    #pragma unroll
    for (int it = 0; it < 2; it++) {
        int i = tid + it * 256;
        if (i < 384) {
            int r  = i >> 3;
            int xq = i & 7;
            float4 v = *(const float4*)(src + (size_t)r * (RES * RES) + y * RES + xbase + 4 * xq);
            sh[4 * xq + 0][r] = v.x;
            sh[4 * xq + 1][r] = v.y;
            sh[4 * xq + 2][r] = v.z;
            sh[4 * xq + 3][r] = v.w;
        }
    }
    __syncthreads();

    // Write: thread handles (x, 8-rank group g) -> one uint4 (4 half2)
    const size_t obase = ((size_t)(pl * RES + y) * RES + xbase) * RP2;
    const int x = tid >> 3;
    const int g = tid & 7;
    uint4 outv = make_uint4(0u, 0u, 0u, 0u);
    if (g < 6) {
        __half2 h0 = __floats2half2_rn(sh[x][8 * g + 0], sh[x][8 * g + 1]);
        __half2 h1 = __floats2half2_rn(sh[x][8 * g + 2], sh[x][8 * g + 3]);
        __half2 h2 = __floats2half2_rn(sh[x][8 * g + 4], sh[x][8 * g + 5]);
        __half2 h3 = __floats2half2_rn(sh[x][8 * g + 6], sh[x][8 * g + 7]);
        outv.x = *(unsigned*)&h0; outv.y = *(unsigned*)&h1;
        outv.z = *(unsigned*)&h2; outv.w = *(unsigned*)&h3;
    }
    *(uint4*)(&g_tplanes[obase + (size_t)x * RP2 + 4 * g]) = outv;
}

// ---------------------------------------------------------------------------
// Transpose lines: [48,512] fp32 -> [512,64] half.
// ---------------------------------------------------------------------------
__global__ __launch_bounds__(256) void transpose_lines(
    const float* __restrict__ lz, const float* __restrict__ ly,
    const float* __restrict__ lx)
{
    int idx = blockIdx.x * 256 + threadIdx.x;       // 0..49151
    int pl  = idx >> 14;
    int rem = idx & 16383;
    int y   = rem >> 5;
    int rp  = rem & 31;
    const float* src = (pl == 0) ? lz : ((pl == 1) ? ly : lx);
    float a = 0.f, b = 0.f;
    if (rp < 24) { a = src[(2 * rp) * RES + y]; b = src[(2 * rp + 1) * RES + y]; }
    g_tlines[idx] = __floats2half2_rn(a, b);
}

// ---------------------------------------------------------------------------
// Sampling kernel: 8 lanes per point; all 18 loads issued up-front.
// ---------------------------------------------------------------------------
struct Axis { int i0, i1; float w; };

__device__ __forceinline__ Axis make_axis(float c) {
    float t = c * 2.f - 1.f;                       // replicate reference math
    float p = (t + 1.f) * 0.5f * (float)(RES - 1);
    p = fminf(fmaxf(p, 0.f), (float)(RES - 1));
    float f = floorf(p);
    Axis a;
    a.i0 = (int)f;
    a.i1 = min(a.i0 + 1, RES - 1);
    a.w  = p - f;
    return a;
}

// interp one plane's 4 taps + line lerp, accumulate into vm (fp32 pairs)
__device__ __forceinline__ void interp_accum(
    const uint4& t00, const uint4& t01, const uint4& t10, const uint4& t11,
    const uint4& L0,  const uint4& L1,
    float wr, float wc, float wl, float2* vm)
{
    const __half2 hw00 = __float2half2_rn((1.f - wr) * (1.f - wc));
    const __half2 hw01 = __float2half2_rn((1.f - wr) * wc);
    const __half2 hw10 = __float2half2_rn(wr * (1.f - wc));
    const __half2 hw11 = __float2half2_rn(wr * wc);
    const __half2 hwl  = __float2half2_rn(wl);

    const __half2* a00 = (const __half2*)&t00;
    const __half2* a01 = (const __half2*)&t01;
    const __half2* a10 = (const __half2*)&t10;
    const __half2* a11 = (const __half2*)&t11;
    const __half2* l0p = (const __half2*)&L0;
    const __half2* l1p = (const __half2*)&L1;

    #pragma unroll
    for (int k = 0; k < 4; k++) {
        __half2 v = __hmul2(hw00, a00[k]);
        v = __hfma2(hw01, a01[k], v);
        v = __hfma2(hw10, a10[k], v);
        v = __hfma2(hw11, a11[k], v);
        __half2 l = __hfma2(hwl, __hsub2(l1p[k], l0p[k]), l0p[k]);
        float2 p = __half22float2(__hmul2(v, l));
        vm[k] = fadd2(vm[k], p);
    }
}

__global__ __launch_bounds__(256) void geo_sample(
    const float* __restrict__ coords,
    const float* __restrict__ W,      // [32,48]
    const float* __restrict__ B,      // [32]
    float* __restrict__ out,          // [N,32]
    int npts)
{
    __shared__ float2 Wpair[24][32];  // Wpair[rp][o] = (W[o][2rp], W[o][2rp+1])
    __shared__ float  vmsh[32][68];   // padded: conflict-free f32x2 reads
    __shared__ float  bsh[32];

    const int tid = threadIdx.x;
    for (int i = tid; i < 768; i += 256) {
        int o = i & 31, rp = i >> 5;
        Wpair[rp][o] = make_float2(W[o * 48 + 2 * rp], W[o * 48 + 2 * rp + 1]);
    }
    if (tid < 32) bsh[tid] = B[tid];
    __syncthreads();

    const int sub = tid & 7;          // rank octet
    const int lpt = tid >> 3;         // local point 0..31
    const int pt  = blockIdx.x * 32 + lpt;
    const bool valid = (pt < npts);

    float cx = 0.f, cy = 0.f, cz = 0.f;
    if (valid) {
        cx = coords[pt * 3 + 0];
        cy = coords[pt * 3 + 1];
        cz = coords[pt * 3 + 2];
    }
    Axis ax = make_axis(cx);
    Axis ay = make_axis(cy);
    Axis az = make_axis(cz);

    const int s4 = sub * 4;

    // ---- compute all 12 tap offsets + 6 line offsets -----------------------
    // plane 0 (xy): row=ay, col=ax, line z
    // plane 1 (xz): row=az, col=ax, line y
    // plane 2 (yz): row=az, col=ay, line x
    const int pb0 = 0 * (RES * RES * RP2);
    const int pb1 = 1 * (RES * RES * RP2);
    const int pb2 = 2 * (RES * RES * RP2);

    const int oA00 = pb0 + (ay.i0 * RES + ax.i0) * RP2 + s4;
    const int oA01 = pb0 + (ay.i0 * RES + ax.i1) * RP2 + s4;
    const int oA10 = pb0 + (ay.i1 * RES + ax.i0) * RP2 + s4;
    const int oA11 = pb0 + (ay.i1 * RES + ax.i1) * RP2 + s4;

    const int oB00 = pb1 + (az.i0 * RES + ax.i0) * RP2 + s4;
    const int oB01 = pb1 + (az.i0 * RES + ax.i1) * RP2 + s4;
    const int oB10 = pb1 + (az.i1 * RES + ax.i0) * RP2 + s4;
    const int oB11 = pb1 + (az.i1 * RES + ax.i1) * RP2 + s4;

    const int oC00 = pb2 + (az.i0 * RES + ay.i0) * RP2 + s4;
    const int oC01 = pb2 + (az.i0 * RES + ay.i1) * RP2 + s4;
    const int oC10 = pb2 + (az.i1 * RES + ay.i0) * RP2 + s4;
    const int oC11 = pb2 + (az.i1 * RES + ay.i1) * RP2 + s4;

    const int lbz = 0 * (RES * RP2) + s4;
    const int lby = 1 * (RES * RP2) + s4;
    const int lbx = 2 * (RES * RP2) + s4;

    // ---- issue ALL loads back-to-back (MLP = 18 per lane) ------------------
    uint4 tA00 = __ldcg((const uint4*)(g_tplanes + oA00));
    uint4 tA01 = __ldcg((const uint4*)(g_tplanes + oA01));
    uint4 tA10 = __ldcg((const uint4*)(g_tplanes + oA10));
    uint4 tA11 = __ldcg((const uint4*)(g_tplanes + oA11));
    uint4 tB00 = __ldcg((const uint4*)(g_tplanes + oB00));
    uint4 tB01 = __ldcg((const uint4*)(g_tplanes + oB01));
    uint4 tB10 = __ldcg((const uint4*)(g_tplanes + oB10));
    uint4 tB11 = __ldcg((const uint4*)(g_tplanes + oB11));
    uint4 tC00 = __ldcg((const uint4*)(g_tplanes + oC00));
    uint4 tC01 = __ldcg((const uint4*)(g_tplanes + oC01));
    uint4 tC10 = __ldcg((const uint4*)(g_tplanes + oC10));
    uint4 tC11 = __ldcg((const uint4*)(g_tplanes + oC11));

    uint4 LZ0 = *(const uint4*)(g_tlines + lbz + az.i0 * RP2);
    uint4 LZ1 = *(const uint4*)(g_tlines + lbz + az.i1 * RP2);
    uint4 LY0 = *(const uint4*)(g_tlines + lby + ay.i0 * RP2);
    uint4 LY1 = *(const uint4*)(g_tlines + lby + ay.i1 * RP2);
    uint4 LX0 = *(const uint4*)(g_tlines + lbx + ax.i0 * RP2);
    uint4 LX1 = *(const uint4*)(g_tlines + lbx + ax.i1 * RP2);

    // ---- interpolate + accumulate ------------------------------------------
    float2 vm[4];
    #pragma unroll
    for (int k = 0; k < 4; k++) vm[k] = make_float2(0.f, 0.f);

    interp_accum(tA00, tA01, tA10, tA11, LZ0, LZ1, ay.w, ax.w, az.w, vm);
    interp_accum(tB00, tB01, tB10, tB11, LY0, LY1, az.w, ax.w, ay.w, vm);
    interp_accum(tC00, tC01, tC10, tC11, LX0, LX1, az.w, ay.w, ax.w, vm);

    // stage vm octet to smem
    *(float4*)&vmsh[lpt][sub * 8]     = make_float4(vm[0].x, vm[0].y, vm[1].x, vm[1].y);
    *(float4*)&vmsh[lpt][sub * 8 + 4] = make_float4(vm[2].x, vm[2].y, vm[3].x, vm[3].y);
    __syncwarp();

    // matvec: each lane produces outputs o = 4*sub .. 4*sub+3 via FFMA2
    float2 a0 = make_float2(0.f, 0.f), a1 = a0, a2 = a0, a3 = a0;
    #pragma unroll
    for (int rp = 0; rp < 24; rp++) {
        float2 v  = *(const float2*)&vmsh[lpt][2 * rp];
        float4 wA = *(const float4*)&Wpair[rp][sub * 4];
        float4 wB = *(const float4*)&Wpair[rp][sub * 4 + 2];
        a0 = ffma2(v, make_float2(wA.x, wA.y), a0);
        a1 = ffma2(v, make_float2(wA.z, wA.w), a1);
        a2 = ffma2(v, make_float2(wB.x, wB.y), a2);
        a3 = ffma2(v, make_float2(wB.z, wB.w), a3);
    }

    if (valid) {
        const int o0 = sub * 4;
        float4 res;
        res.x = a0.x + a0.y + bsh[o0 + 0];
        res.y = a1.x + a1.y + bsh[o0 + 1];
        res.z = a2.x + a2.y + bsh[o0 + 2];
        res.w = a3.x + a3.y + bsh[o0 + 3];
        *(float4*)(out + (size_t)pt * 32 + o0) = res;
    }
}

// ---------------------------------------------------------------------------
extern "C" void kernel_launch(void* const* d_in, const int* in_sizes, int n_in,
                              void* d_out, int out_size)
{
    const float* coords  = (const float*)d_in[0];
    const float* pxy     = (const float*)d_in[1];
    const float* pxz     = (const float*)d_in[2];
    const float* pyz     = (const float*)d_in[3];
    const float* lz      = (const float*)d_in[4];
    const float* ly      = (const float*)d_in[5];
    const float* lx      = (const float*)d_in[6];
    const float* projw   = (const float*)d_in[7];
    const float* projb   = (const float*)d_in[8];
    float* out = (float*)d_out;

    const int npts = in_sizes[0] / 3;

    transpose_planes<<<dim3(16, 512, 3), 256>>>(pxy, pxz, pyz);
    transpose_lines<<<192, 256>>>(lz, ly, lx);

    const int nblocks = (npts + 31) / 32;
    geo_sample<<<nblocks, 256>>>(coords, projw, projb, out, npts);
}

// round 5
// speedup vs baseline: 1.6029x; 1.5441x over previous
#include <cuda_runtime.h>
#include <cuda_fp16.h>
#include <cstdint>

// ---------------------------------------------------------------------------
// GeoEncoder: tri-plane + line sampling, rank 48 (padded to 64), OUT=32.
//   1) transpose planes [48,512,512] fp32 -> [512,512,64] half (zero-padded):
//      one (y,x) tap == one 128B line (96MB, mostly L2 resident).
//   2) transpose lines  [48,512] fp32 -> [512,64] half (192KB).
//   3) geo_sample: 8 lanes per point for gather/interp (lane owns 8-rank
//      octet, all 18 loads issued up-front), then matvec with ONE OUTPUT
//      PER LANE: weight row in 48 registers, vm read via broadcast LDS.
//      (R5: removes ~23KB/warp of redundant smem weight traffic.)
// ---------------------------------------------------------------------------

#define RES 512
#define RP2 32                // half2 per (y,x) texel (64 halves = 128B)

__device__ __align__(128) __half2 g_tplanes[(size_t)3 * RES * RES * RP2];
__device__ __align__(128) __half2 g_tlines[3 * RES * RP2];

// ---- packed fp32x2 helpers (Blackwell FFMA2) ------------------------------
__device__ __forceinline__ float2 ffma2(float2 a, float2 b, float2 c) {
    unsigned long long A = *reinterpret_cast<unsigned long long*>(&a);
    unsigned long long B = *reinterpret_cast<unsigned long long*>(&b);
    unsigned long long C = *reinterpret_cast<unsigned long long*>(&c);
    unsigned long long D;
    asm("fma.rn.f32x2 %0, %1, %2, %3;" : "=l"(D) : "l"(A), "l"(B), "l"(C));
    return *reinterpret_cast<float2*>(&D);
}
__device__ __forceinline__ float2 fadd2(float2 a, float2 b) {
    unsigned long long A = *reinterpret_cast<unsigned long long*>(&a);
    unsigned long long B = *reinterpret_cast<unsigned long long*>(&b);
    unsigned long long D;
    asm("add.rn.f32x2 %0, %1, %2;" : "=l"(D) : "l"(A), "l"(B));
    return *reinterpret_cast<float2*>(&D);
}

// ---------------------------------------------------------------------------
// Transpose planes: float4 loads, uint4 stores. grid (16,512,3), block 256.
// ---------------------------------------------------------------------------
__global__ __launch_bounds__(256) void transpose_planes(
    const float* __restrict__ p0, const float* __restrict__ p1,
    const float* __restrict__ p2)
{
    __shared__ float sh[32][49];   // [x][r]
    const int xbase = blockIdx.x * 32;
    const int y     = blockIdx.y;
    const int pl    = blockIdx.z;
    const float* __restrict__ src = (pl == 0) ? p0 : ((pl == 1) ? p1 : p2);
    const int tid = threadIdx.x;

    #pragma unroll
    for (int it = 0; it < 2; it++) {
        int i = tid + it * 256;
        if (i < 384) {
            int r  = i >> 3;
            int xq = i & 7;
            float4 v = *(const float4*)(src + (size_t)r * (RES * RES) + y * RES + xbase + 4 * xq);
            sh[4 * xq + 0][r] = v.x;
            sh[4 * xq + 1][r] = v.y;
            sh[4 * xq + 2][r] = v.z;
            sh[4 * xq + 3][r] = v.w;
        }
    }
    __syncthreads();

    const size_t obase = ((size_t)(pl * RES + y) * RES + xbase) * RP2;
    const int x = tid >> 3;
    const int g = tid & 7;
    uint4 outv = make_uint4(0u, 0u, 0u, 0u);
    if (g < 6) {
        __half2 h0 = __floats2half2_rn(sh[x][8 * g + 0], sh[x][8 * g + 1]);
        __half2 h1 = __floats2half2_rn(sh[x][8 * g + 2], sh[x][8 * g + 3]);
        __half2 h2 = __floats2half2_rn(sh[x][8 * g + 4], sh[x][8 * g + 5]);
        __half2 h3 = __floats2half2_rn(sh[x][8 * g + 6], sh[x][8 * g + 7]);
        outv.x = *(unsigned*)&h0; outv.y = *(unsigned*)&h1;
        outv.z = *(unsigned*)&h2; outv.w = *(unsigned*)&h3;
    }
    *(uint4*)(&g_tplanes[obase + (size_t)x * RP2 + 4 * g]) = outv;
}

// ---------------------------------------------------------------------------
// Transpose lines: [48,512] fp32 -> [512,64] half.
// ---------------------------------------------------------------------------
__global__ __launch_bounds__(256) void transpose_lines(
    const float* __restrict__ lz, const float* __restrict__ ly,
    const float* __restrict__ lx)
{
    int idx = blockIdx.x * 256 + threadIdx.x;       // 0..49151
    int pl  = idx >> 14;
    int rem = idx & 16383;
    int y   = rem >> 5;
    int rp  = rem & 31;
    const float* src = (pl == 0) ? lz : ((pl == 1) ? ly : lx);
    float a = 0.f, b = 0.f;
    if (rp < 24) { a = src[(2 * rp) * RES + y]; b = src[(2 * rp + 1) * RES + y]; }
    g_tlines[idx] = __floats2half2_rn(a, b);
}

// ---------------------------------------------------------------------------
// Sampling kernel
// ---------------------------------------------------------------------------
struct Axis { int i0, i1; float w; };

__device__ __forceinline__ Axis make_axis(float c) {
    float t = c * 2.f - 1.f;
    float p = (t + 1.f) * 0.5f * (float)(RES - 1);
    p = fminf(fmaxf(p, 0.f), (float)(RES - 1));
    float f = floorf(p);
    Axis a;
    a.i0 = (int)f;
    a.i1 = min(a.i0 + 1, RES - 1);
    a.w  = p - f;
    return a;
}

__device__ __forceinline__ void interp_accum(
    const uint4& t00, const uint4& t01, const uint4& t10, const uint4& t11,
    const uint4& L0,  const uint4& L1,
    float wr, float wc, float wl, float2* vm)
{
    const __half2 hw00 = __float2half2_rn((1.f - wr) * (1.f - wc));
    const __half2 hw01 = __float2half2_rn((1.f - wr) * wc);
    const __half2 hw10 = __float2half2_rn(wr * (1.f - wc));
    const __half2 hw11 = __float2half2_rn(wr * wc);
    const __half2 hwl  = __float2half2_rn(wl);

    const __half2* a00 = (const __half2*)&t00;
    const __half2* a01 = (const __half2*)&t01;
    const __half2* a10 = (const __half2*)&t10;
    const __half2* a11 = (const __half2*)&t11;
    const __half2* l0p = (const __half2*)&L0;
    const __half2* l1p = (const __half2*)&L1;

    #pragma unroll
    for (int k = 0; k < 4; k++) {
        __half2 v = __hmul2(hw00, a00[k]);
        v = __hfma2(hw01, a01[k], v);
        v = __hfma2(hw10, a10[k], v);
        v = __hfma2(hw11, a11[k], v);
        __half2 l = __hfma2(hwl, __hsub2(l1p[k], l0p[k]), l0p[k]);
        float2 p = __half22float2(__hmul2(v, l));
        vm[k] = fadd2(vm[k], p);
    }
}

__global__ __launch_bounds__(256) void geo_sample(
    const float* __restrict__ coords,
    const float* __restrict__ W,      // [32,48]
    const float* __restrict__ B,      // [32]
    float* __restrict__ out,          // [N,32]
    int npts)
{
    __shared__ float2 Wpair[24][32];  // Wpair[rp][o] = (W[o][2rp], W[o][2rp+1])
    __shared__ float  vmsh[32][68];   // per-point vm rows (padded)
    __shared__ float  bsh[32];

    const int tid = threadIdx.x;
    for (int i = tid; i < 768; i += 256) {
        int o = i & 31, rp = i >> 5;
        Wpair[rp][o] = make_float2(W[o * 48 + 2 * rp], W[o * 48 + 2 * rp + 1]);
    }
    if (tid < 32) bsh[tid] = B[tid];
    __syncthreads();

    const int sub = tid & 7;          // rank octet
    const int lpt = tid >> 3;         // local point 0..31
    const int pt  = blockIdx.x * 32 + lpt;
    const bool valid = (pt < npts);

    float cx = 0.f, cy = 0.f, cz = 0.f;
    if (valid) {
        cx = coords[pt * 3 + 0];
        cy = coords[pt * 3 + 1];
        cz = coords[pt * 3 + 2];
    }
    Axis ax = make_axis(cx);
    Axis ay = make_axis(cy);
    Axis az = make_axis(cz);

    const int s4 = sub * 4;

    const int pb0 = 0 * (RES * RES * RP2);
    const int pb1 = 1 * (RES * RES * RP2);
    const int pb2 = 2 * (RES * RES * RP2);

    const int oA00 = pb0 + (ay.i0 * RES + ax.i0) * RP2 + s4;
    const int oA01 = pb0 + (ay.i0 * RES + ax.i1) * RP2 + s4;
    const int oA10 = pb0 + (ay.i1 * RES + ax.i0) * RP2 + s4;
    const int oA11 = pb0 + (ay.i1 * RES + ax.i1) * RP2 + s4;

    const int oB00 = pb1 + (az.i0 * RES + ax.i0) * RP2 + s4;
    const int oB01 = pb1 + (az.i0 * RES + ax.i1) * RP2 + s4;
    const int oB10 = pb1 + (az.i1 * RES + ax.i0) * RP2 + s4;
    const int oB11 = pb1 + (az.i1 * RES + ax.i1) * RP2 + s4;

    const int oC00 = pb2 + (az.i0 * RES + ay.i0) * RP2 + s4;
    const int oC01 = pb2 + (az.i0 * RES + ay.i1) * RP2 + s4;
    const int oC10 = pb2 + (az.i1 * RES + ay.i0) * RP2 + s4;
    const int oC11 = pb2 + (az.i1 * RES + ay.i1) * RP2 + s4;

    const int lbz = 0 * (RES * RP2) + s4;
    const int lby = 1 * (RES * RP2) + s4;
    const int lbx = 2 * (RES * RP2) + s4;

    // issue ALL 18 loads back-to-back (MLP = 18 per lane)
    uint4 tA00 = __ldcg((const uint4*)(g_tplanes + oA00));
    uint4 tA01 = __ldcg((const uint4*)(g_tplanes + oA01));
    uint4 tA10 = __ldcg((const uint4*)(g_tplanes + oA10));
    uint4 tA11 = __ldcg((const uint4*)(g_tplanes + oA11));
    uint4 tB00 = __ldcg((const uint4*)(g_tplanes + oB00));
    uint4 tB01 = __ldcg((const uint4*)(g_tplanes + oB01));
    uint4 tB10 = __ldcg((const uint4*)(g_tplanes + oB10));
    uint4 tB11 = __ldcg((const uint4*)(g_tplanes + oB11));
    uint4 tC00 = __ldcg((const uint4*)(g_tplanes + oC00));
    uint4 tC01 = __ldcg((const uint4*)(g_tplanes + oC01));
    uint4 tC10 = __ldcg((const uint4*)(g_tplanes + oC10));
    uint4 tC11 = __ldcg((const uint4*)(g_tplanes + oC11));

    uint4 LZ0 = *(const uint4*)(g_tlines + lbz + az.i0 * RP2);
    uint4 LZ1 = *(const uint4*)(g_tlines + lbz + az.i1 * RP2);
    uint4 LY0 = *(const uint4*)(g_tlines + lby + ay.i0 * RP2);
    uint4 LY1 = *(const uint4*)(g_tlines + lby + ay.i1 * RP2);
    uint4 LX0 = *(const uint4*)(g_tlines + lbx + ax.i0 * RP2);
    uint4 LX1 = *(const uint4*)(g_tlines + lbx + ax.i1 * RP2);

    float2 vm[4];
    #pragma unroll
    for (int k = 0; k < 4; k++) vm[k] = make_float2(0.f, 0.f);

    interp_accum(tA00, tA01, tA10, tA11, LZ0, LZ1, ay.w, ax.w, az.w, vm);
    interp_accum(tB00, tB01, tB10, tB11, LY0, LY1, az.w, ax.w, ay.w, vm);
    interp_accum(tC00, tC01, tC10, tC11, LX0, LX1, az.w, ay.w, ax.w, vm);

    // stage vm octet to smem
    *(float4*)&vmsh[lpt][sub * 8]     = make_float4(vm[0].x, vm[0].y, vm[1].x, vm[1].y);
    *(float4*)&vmsh[lpt][sub * 8 + 4] = make_float4(vm[2].x, vm[2].y, vm[3].x, vm[3].y);
    __syncwarp();

    // ---- matvec, R5 layout: lane = output channel --------------------------
    // Each lane holds W[lane][0..47] in 24 float2 registers (read once),
    // vm pairs come in as warp-broadcast LDS.64 reads.
    const int lane = tid & 31;        // output channel
    const int wrp  = tid >> 5;        // warp id: owns points 4*wrp..4*wrp+3

    float2 wreg[24];
    #pragma unroll
    for (int rp = 0; rp < 24; rp++) wreg[rp] = Wpair[rp][lane];
    const float bias = bsh[lane];

    const int ptbase = blockIdx.x * 32 + (wrp << 2);
    #pragma unroll
    for (int p = 0; p < 4; p++) {
        const int lp = (wrp << 2) + p;
        float2 acc = make_float2(0.f, 0.f);
        #pragma unroll
        for (int rp = 0; rp < 24; rp++) {
            float2 v = *(const float2*)&vmsh[lp][2 * rp];   // broadcast
            acc = ffma2(v, wreg[rp], acc);
        }
        const int ptg = ptbase + p;
        if (ptg < npts)
            out[(size_t)ptg * 32 + lane] = acc.x + acc.y + bias;
    }
}

// ---------------------------------------------------------------------------
extern "C" void kernel_launch(void* const* d_in, const int* in_sizes, int n_in,
                              void* d_out, int out_size)
{
    const float* coords  = (const float*)d_in[0];
    const float* pxy     = (const float*)d_in[1];
    const float* pxz     = (const float*)d_in[2];
    const float* pyz     = (const float*)d_in[3];
    const float* lz      = (const float*)d_in[4];
    const float* ly      = (const float*)d_in[5];
    const float* lx      = (const float*)d_in[6];
    const float* projw   = (const float*)d_in[7];
    const float* projb   = (const float*)d_in[8];
    float* out = (float*)d_out;

    const int npts = in_sizes[0] / 3;

    transpose_planes<<<dim3(16, 512, 3), 256>>>(pxy, pxz, pyz);
    transpose_lines<<<192, 256>>>(lz, ly, lx);

    const int nblocks = (npts + 31) / 32;
    geo_sample<<<nblocks, 256>>>(coords, projw, projb, out, npts);
}